// round 16
// baseline (speedup 1.0000x reference)
#include <cuda_runtime.h>
#include <cuda_bf16.h>
#include <cstdint>

// ==================== scratch (no cudaMalloc allowed) ====================
__device__ __nv_bfloat16 g_xqh[4194304], g_xql[4194304];
__device__ __nv_bfloat16 g_xkh[4194304], g_xkl[4194304];
__device__ __nv_bfloat16 g_xvh[4194304], g_xvl[4194304];
__device__ __nv_bfloat16 g_wqh[1048576], g_wql[1048576];
__device__ __nv_bfloat16 g_wkh[1048576], g_wkl[1048576];
__device__ __nv_bfloat16 g_wvh[1048576], g_wvl[1048576];
__device__ __nv_bfloat16 g_woh[1048576], g_wol[1048576];
__device__ __nv_bfloat16 g_qh[4194304], g_ql[4194304];
__device__ __nv_bfloat16 g_kh[4194304], g_kl[4194304];
__device__ __nv_bfloat16 g_vh[4194304], g_vl[4194304];
__device__ __nv_bfloat16 g_ah[4194304], g_al[4194304];

// ==================== helpers ====================
__device__ __forceinline__ uint32_t smem_u32(const void* p) {
    uint32_t a;
    asm("{ .reg .u64 t; cvta.to.shared.u64 t, %1; cvt.u32.u64 %0, t; }"
        : "=r"(a) : "l"(p));
    return a;
}
__device__ __forceinline__ void cp16(uint32_t s, const void* g) {
    asm volatile("cp.async.cg.shared.global [%0], [%1], 16;" :: "r"(s), "l"(g));
}
#define CP_COMMIT() asm volatile("cp.async.commit_group;" ::: "memory")

__device__ __forceinline__ void ldsm4(uint32_t& r0, uint32_t& r1,
                                      uint32_t& r2, uint32_t& r3, uint32_t a) {
    asm volatile("ldmatrix.sync.aligned.m8n8.x4.shared.b16 {%0,%1,%2,%3}, [%4];"
                 : "=r"(r0), "=r"(r1), "=r"(r2), "=r"(r3) : "r"(a));
}
__device__ __forceinline__ void ldsm4t(uint32_t& r0, uint32_t& r1,
                                       uint32_t& r2, uint32_t& r3, uint32_t a) {
    asm volatile("ldmatrix.sync.aligned.m8n8.x4.trans.shared.b16 {%0,%1,%2,%3}, [%4];"
                 : "=r"(r0), "=r"(r1), "=r"(r2), "=r"(r3) : "r"(a));
}
__device__ __forceinline__ void mma16816(float* d, const uint32_t* a,
                                         uint32_t b0, uint32_t b1) {
    asm volatile("mma.sync.aligned.m16n8k16.row.col.f32.bf16.bf16.f32 "
                 "{%0,%1,%2,%3}, {%4,%5,%6,%7}, {%8,%9}, {%0,%1,%2,%3};"
                 : "+f"(d[0]), "+f"(d[1]), "+f"(d[2]), "+f"(d[3])
                 : "r"(a[0]), "r"(a[1]), "r"(a[2]), "r"(a[3]), "r"(b0), "r"(b1));
}
__device__ __forceinline__ uint32_t packbf2(float x0, float x1) {
    uint32_t r;
    asm("cvt.rn.bf16x2.f32 %0, %1, %2;" : "=r"(r) : "f"(x1), "f"(x0));
    return r;
}

// ==================== merged fp32 -> (hi, lo) bf16 splits ====================
__global__ void conv_split3(const float* __restrict__ q,
                            const float* __restrict__ k,
                            const float* __restrict__ v, int n4) {
    int i = blockIdx.x * blockDim.x + threadIdx.x;
    if (i >= n4) return;
    const int z = blockIdx.z;
    const float* in = (z == 0) ? q : (z == 1) ? k : v;
    __nv_bfloat16* hi = (z == 0) ? g_xqh : (z == 1) ? g_xkh : g_xvh;
    __nv_bfloat16* lo = (z == 0) ? g_xql : (z == 1) ? g_xkl : g_xvl;
    float4 x = ((const float4*)in)[i];
    __nv_bfloat16 h0 = __float2bfloat16(x.x), h1 = __float2bfloat16(x.y);
    __nv_bfloat16 h2 = __float2bfloat16(x.z), h3 = __float2bfloat16(x.w);
    ((__nv_bfloat162*)hi)[2 * i + 0] = __nv_bfloat162(h0, h1);
    ((__nv_bfloat162*)hi)[2 * i + 1] = __nv_bfloat162(h2, h3);
    ((__nv_bfloat162*)lo)[2 * i + 0] = __nv_bfloat162(
        __float2bfloat16(x.x - __bfloat162float(h0)),
        __float2bfloat16(x.y - __bfloat162float(h1)));
    ((__nv_bfloat162*)lo)[2 * i + 1] = __nv_bfloat162(
        __float2bfloat16(x.z - __bfloat162float(h2)),
        __float2bfloat16(x.w - __bfloat162float(h3)));
}

__global__ void convT_split4(const float* __restrict__ Wq,
                             const float* __restrict__ Wk,
                             const float* __restrict__ Wv,
                             const float* __restrict__ Wo) {
    __shared__ float t[32][33];
    const int z = blockIdx.z;
    const float* W = (z == 0) ? Wq : (z == 1) ? Wk : (z == 2) ? Wv : Wo;
    __nv_bfloat16* hi = (z == 0) ? g_wqh : (z == 1) ? g_wkh : (z == 2) ? g_wvh : g_woh;
    __nv_bfloat16* lo = (z == 0) ? g_wql : (z == 1) ? g_wkl : (z == 2) ? g_wvl : g_wol;
    int n0 = blockIdx.x * 32, k0 = blockIdx.y * 32;
    int tx = threadIdx.x, ty = threadIdx.y;
    #pragma unroll
    for (int i = 0; i < 4; i++)
        t[ty + 8 * i][tx] = W[(size_t)(k0 + ty + 8 * i) * 1024 + n0 + tx];
    __syncthreads();
    #pragma unroll
    for (int i = 0; i < 4; i++) {
        float a = t[tx][ty + 8 * i];
        __nv_bfloat16 h = __float2bfloat16(a);
        size_t o = (size_t)(n0 + ty + 8 * i) * 1024 + k0 + tx;
        hi[o] = h;
        lo[o] = __float2bfloat16(a - __bfloat162float(h));
    }
}

// ==================== GEMM mainloop: 3-stage pipeline, 1 barrier/chunk =======
// mma/ldsm body byte-identical to the R6/R12 proven loop; only the staging
// and barrier schedule changed.
// Safety of single barrier: prefetch at iter ch writes stage (ch+2)%3, whose
// last readers (compute ch-1) passed this iter's barrier; the previous write
// group to that stage (G(ch-1)) completed at iter ch-1's wait_group.
#define TILE_B   10240               // 128 * 80
#define STAGE_B  40960               // 4 tiles
#define N_STAGE  3

#define GEMM_PREFETCH(CH, STG)                                                 \
    do {                                                                       \
        const uint32_t dst_ = sb + (uint32_t)(STG) * STAGE_B;                  \
        const int k0_ = (CH) * 32;                                             \
        _Pragma("unroll")                                                      \
        for (int t = 0; t < 4; t++)                                            \
            _Pragma("unroll")                                                  \
            for (int i = 0; i < 2; i++) {                                      \
                int r = r_ld + i * 64;                                         \
                cp16(dst_ + t * TILE_B + r * 80 + c_ld * 16,                   \
                     srcs[t] + (size_t)r * 1024 + k0_ + c_ld * 8);             \
            }                                                                  \
        CP_COMMIT();                                                           \
    } while (0)

#define GEMM_MAINLOOP()                                                        \
    const int frow = ((lane >> 3) & 1) * 8 + (lane & 7);                       \
    const int fchk = lane >> 4;                                                \
    const uint32_t aoff = (uint32_t)((warp_m * 32 + frow) * 80 + fchk * 16);   \
    const uint32_t boff = (uint32_t)((warp_n * 64 + frow) * 80 + fchk * 16);   \
    const int r_ld = tid >> 2, c_ld = tid & 3;                                 \
    float acc[2][8][4];                                                        \
    _Pragma("unroll")                                                          \
    for (int mf = 0; mf < 2; mf++)                                             \
        _Pragma("unroll")                                                      \
        for (int nf = 0; nf < 8; nf++)                                         \
            _Pragma("unroll")                                                  \
            for (int e = 0; e < 4; e++) acc[mf][nf][e] = 0.0f;                 \
    GEMM_PREFETCH(0, 0);                                                       \
    GEMM_PREFETCH(1, 1);                                                       \
    int stg = 0, stg2 = 2;                                                     \
    for (int ch = 0; ch < 32; ch++) {                                          \
        if (ch < 31) {                                                         \
            asm volatile("cp.async.wait_group 1;" ::: "memory");               \
        } else {                                                               \
            asm volatile("cp.async.wait_group 0;" ::: "memory");               \
        }                                                                      \
        __syncthreads();                                                       \
        if (ch + 2 < 32) GEMM_PREFETCH(ch + 2, stg2);                          \
        const uint32_t stage = sb + (uint32_t)stg * STAGE_B;                   \
        _Pragma("unroll")                                                      \
        for (int term = 0; term < 3; term++) {                                 \
            const uint32_t sA = stage + (term == 2 ? TILE_B : 0u);             \
            const uint32_t sB = stage + 2u * TILE_B + (term == 1 ? TILE_B : 0u); \
            _Pragma("unroll")                                                  \
            for (int ks = 0; ks < 2; ks++) {                                   \
                uint32_t a[2][4];                                              \
                ldsm4(a[0][0], a[0][1], a[0][2], a[0][3], sA + aoff + ks * 32);\
                ldsm4(a[1][0], a[1][1], a[1][2], a[1][3],                      \
                      sA + aoff + 1280 + ks * 32);                             \
                uint32_t b[4][4];                                              \
                _Pragma("unroll")                                              \
                for (int nfp = 0; nfp < 4; nfp++)                              \
                    ldsm4(b[nfp][0], b[nfp][1], b[nfp][2], b[nfp][3],          \
                          sB + boff + nfp * 1280 + ks * 32);                   \
                _Pragma("unroll")                                              \
                for (int mf = 0; mf < 2; mf++)                                 \
                    _Pragma("unroll")                                          \
                    for (int nfp = 0; nfp < 4; nfp++) {                        \
                        mma16816(acc[mf][2 * nfp],     a[mf], b[nfp][0], b[nfp][2]); \
                        mma16816(acc[mf][2 * nfp + 1], a[mf], b[nfp][1], b[nfp][3]); \
                    }                                                          \
            }                                                                  \
        }                                                                      \
        stg = (stg == 2) ? 0 : stg + 1;                                        \
        stg2 = (stg2 == 2) ? 0 : stg2 + 1;                                     \
    }

// QKV projections, merged via grid.z. Split-bf16 epilogue.
__global__ void __launch_bounds__(256, 1) tc_gemm_qkv(
    const float* __restrict__ bq, const float* __restrict__ bk,
    const float* __restrict__ bv)
{
    extern __shared__ char smem[];
    const uint32_t sb = smem_u32(smem);
    const int tid = threadIdx.x, wid = tid >> 5, lane = tid & 31;
    const int m0 = blockIdx.y * 128, n0 = blockIdx.x * 128;
    const int warp_m = wid & 3, warp_n = wid >> 2;
    const int z = blockIdx.z;

    const __nv_bfloat16* Ah = (z == 0) ? g_xqh : (z == 1) ? g_xkh : g_xvh;
    const __nv_bfloat16* Al = (z == 0) ? g_xql : (z == 1) ? g_xkl : g_xvl;
    const __nv_bfloat16* Bh = (z == 0) ? g_wqh : (z == 1) ? g_wkh : g_wvh;
    const __nv_bfloat16* Bl = (z == 0) ? g_wql : (z == 1) ? g_wkl : g_wvl;
    const float* bias       = (z == 0) ? bq    : (z == 1) ? bk    : bv;
    __nv_bfloat16* Ch       = (z == 0) ? g_qh  : (z == 1) ? g_kh  : g_vh;
    __nv_bfloat16* Cl       = (z == 0) ? g_ql  : (z == 1) ? g_kl  : g_vl;

    const __nv_bfloat16* srcs[4] = {
        Ah + (size_t)m0 * 1024, Al + (size_t)m0 * 1024,
        Bh + (size_t)n0 * 1024, Bl + (size_t)n0 * 1024 };

    GEMM_MAINLOOP()

    const int rbase = m0 + warp_m * 32 + (lane >> 2);
    const int cbase = n0 + warp_n * 64 + (lane & 3) * 2;
    #pragma unroll
    for (int mf = 0; mf < 2; mf++)
        #pragma unroll
        for (int h = 0; h < 2; h++) {
            int r = rbase + mf * 16 + h * 8;
            #pragma unroll
            for (int nf = 0; nf < 8; nf++) {
                int cc = cbase + nf * 8;
                float x = acc[mf][nf][2 * h + 0] + bias[cc];
                float y = acc[mf][nf][2 * h + 1] + bias[cc + 1];
                __nv_bfloat16 hx = __float2bfloat16(x);
                __nv_bfloat16 hy = __float2bfloat16(y);
                *(__nv_bfloat162*)(Ch + (size_t)r * 1024 + cc) = __nv_bfloat162(hx, hy);
                *(__nv_bfloat162*)(Cl + (size_t)r * 1024 + cc) = __nv_bfloat162(
                    __float2bfloat16(x - __bfloat162float(hx)),
                    __float2bfloat16(y - __bfloat162float(hy)));
            }
        }
}

// Final projection: fp32 out * qmask.
__global__ void __launch_bounds__(256, 1) tc_gemm_final(
    const float* __restrict__ bias, const int* __restrict__ qmask,
    float* __restrict__ C)
{
    extern __shared__ char smem[];
    const uint32_t sb = smem_u32(smem);
    const int tid = threadIdx.x, wid = tid >> 5, lane = tid & 31;
    const int m0 = blockIdx.y * 128, n0 = blockIdx.x * 128;
    const int warp_m = wid & 3, warp_n = wid >> 2;

    const __nv_bfloat16* srcs[4] = {
        g_ah + (size_t)m0 * 1024, g_al + (size_t)m0 * 1024,
        g_woh + (size_t)n0 * 1024, g_wol + (size_t)n0 * 1024 };

    GEMM_MAINLOOP()

    const int rbase = m0 + warp_m * 32 + (lane >> 2);
    const int cbase = n0 + warp_n * 64 + (lane & 3) * 2;
    #pragma unroll
    for (int mf = 0; mf < 2; mf++)
        #pragma unroll
        for (int h = 0; h < 2; h++) {
            int r = rbase + mf * 16 + h * 8;
            float qm = (float)qmask[r];
            #pragma unroll
            for (int nf = 0; nf < 8; nf++) {
                int cc = cbase + nf * 8;
                float2 o;
                o.x = (acc[mf][nf][2 * h + 0] + bias[cc])     * qm;
                o.y = (acc[mf][nf][2 * h + 1] + bias[cc + 1]) * qm;
                *(float2*)(C + (size_t)r * 1024 + cc) = o;
            }
        }
}

// ==================== tensor-core flash attention (R15, 97.4us, unchanged) ===
#define SST 72
#define STB (128 * SST * 2)          // 18432 B per tile

#define LOAD_KV(JT, S) do {                                                   \
    const int kv0_ = (JT) * 128;                                              \
    const __nv_bfloat16* mats_[4] = {                                         \
        g_kh + ((size_t)(b * 1024 + kv0_)) * 1024 + headoff,                  \
        g_kl + ((size_t)(b * 1024 + kv0_)) * 1024 + headoff,                  \
        g_vh + ((size_t)(b * 1024 + kv0_)) * 1024 + headoff,                  \
        g_vl + ((size_t)(b * 1024 + kv0_)) * 1024 + headoff };                \
    uint32_t base_ = sb + (S) * 4 * STB;                                      \
    _Pragma("unroll")                                                         \
    for (int m_ = 0; m_ < 4; m_++)                                            \
        _Pragma("unroll")                                                     \
        for (int i_ = 0; i_ < 4; i_++) {                                      \
            int idx_ = tid + i_ * 256;                                        \
            int r_ = idx_ >> 3, ch_ = idx_ & 7;                               \
            cp16(base_ + m_ * STB + r_ * (SST * 2) + ch_ * 16,                \
                 mats_[m_] + (size_t)r_ * 1024 + ch_ * 8);                    \
        }                                                                     \
    if (tid < 128)                                                            \
        vmadd[(S) * 128 + tid] =                                              \
            vmask[b * 1024 + kv0_ + tid] ? 0.0f : -1.0e12f;                   \
    CP_COMMIT();                                                              \
} while (0)

__global__ void __launch_bounds__(256, 1) attn_tc(const int* __restrict__ vmask)
{
    extern __shared__ char smem[];
    const uint32_t sb = smem_u32(smem);
    float* vmadd = (float*)(smem + 8 * STB);   // [2][128]

    const int bid = blockIdx.x;                // 0..511, LPT: heavy first
    const int it = 7 - (bid >> 6);
    const int bh = bid & 63;
    const int b = bh >> 4, h = bh & 15;
    const int tid = threadIdx.x, wid = tid >> 5, lane = tid & 31;
    const int g = lane >> 2, tg = lane & 3;
    const size_t headoff = (size_t)h * 64;
    const int qrow0 = it * 128;
    const int frow = lane & 15, fchk = lane >> 4;
    const int nt = it + 1;                     // causal: tiles 0..it only

    #pragma unroll
    for (int m = 0; m < 2; m++) {
        const __nv_bfloat16* src =
            (m ? g_ql : g_qh) + ((size_t)(b * 1024 + qrow0)) * 1024 + headoff;
        uint32_t dstb = sb + m * STB;
        #pragma unroll
        for (int i = 0; i < 4; i++) {
            int idx = tid + i * 256;
            int r = idx >> 3, ch = idx & 7;
            cp16(dstb + r * (SST * 2) + ch * 16, src + (size_t)r * 1024 + ch * 8);
        }
    }
    CP_COMMIT();
    asm volatile("cp.async.wait_group 0;" ::: "memory");
    __syncthreads();

    uint32_t qfh[4][4], qfl[4][4];
    {
        uint32_t abase = sb + (wid * 16 + frow) * (SST * 2) + fchk * 16;
        #pragma unroll
        for (int ks = 0; ks < 4; ks++) {
            ldsm4(qfh[ks][0], qfh[ks][1], qfh[ks][2], qfh[ks][3], abase + ks * 32);
            ldsm4(qfl[ks][0], qfl[ks][1], qfl[ks][2], qfl[ks][3],
                  abase + STB + ks * 32);
        }
    }
    __syncthreads();

    float oacc[8][4];
    #pragma unroll
    for (int nf = 0; nf < 8; nf++)
        #pragma unroll
        for (int e = 0; e < 4; e++) oacc[nf][e] = 0.0f;
    float m0r = -3.0e38f, m1r = -3.0e38f, l0r = 0.0f, l1r = 0.0f;

    LOAD_KV(0, 0);

    for (int jt = 0; jt < nt; jt++) {
        if (jt > 0) __syncthreads();
        if (jt + 1 < nt) {
            LOAD_KV(jt + 1, (jt + 1) & 1);
            asm volatile("cp.async.wait_group 1;" ::: "memory");
        } else {
            asm volatile("cp.async.wait_group 0;" ::: "memory");
        }
        __syncthreads();

        const int s = jt & 1;
        const int kv0 = jt * 128;
        const float* vm_s = vmadd + s * 128;
        const uint32_t khb = sb + s * 4 * STB;
        const uint32_t vhb = khb + 2 * STB;

        float sacc[16][4];
        #pragma unroll
        for (int nf = 0; nf < 16; nf++)
            #pragma unroll
            for (int e = 0; e < 4; e++) sacc[nf][e] = 0.0f;

        const uint32_t kaddr = khb + frow * (SST * 2) + fchk * 16;
        #pragma unroll
        for (int ks = 0; ks < 4; ks++)
            #pragma unroll
            for (int nfp = 0; nfp < 8; nfp++) {
                uint32_t off = (uint32_t)(nfp * 16) * (SST * 2) + ks * 32;
                uint32_t b0, b1, b2, b3;
                ldsm4(b0, b1, b2, b3, kaddr + off);
                mma16816(sacc[2 * nfp],     qfh[ks], b0, b2);
                mma16816(sacc[2 * nfp + 1], qfh[ks], b1, b3);
                mma16816(sacc[2 * nfp],     qfl[ks], b0, b2);
                mma16816(sacc[2 * nfp + 1], qfl[ks], b1, b3);
                uint32_t c0, c1, c2, c3;
                ldsm4(c0, c1, c2, c3, kaddr + off + STB);
                mma16816(sacc[2 * nfp],     qfh[ks], c0, c2);
                mma16816(sacc[2 * nfp + 1], qfh[ks], c1, c3);
            }

        const int gr0 = qrow0 + wid * 16 + g, gr1 = gr0 + 8;
        #pragma unroll
        for (int nf = 0; nf < 16; nf++) {
            int c0 = nf * 8 + tg * 2;
            int gc0 = kv0 + c0, gc1 = gc0 + 1;
            float vm0 = vm_s[c0], vm1 = vm_s[c0 + 1];
            sacc[nf][0] = sacc[nf][0] * 0.125f + vm0 + (gc0 > gr0 ? -1.0e12f : 0.0f);
            sacc[nf][1] = sacc[nf][1] * 0.125f + vm1 + (gc1 > gr0 ? -1.0e12f : 0.0f);
            sacc[nf][2] = sacc[nf][2] * 0.125f + vm0 + (gc0 > gr1 ? -1.0e12f : 0.0f);
            sacc[nf][3] = sacc[nf][3] * 0.125f + vm1 + (gc1 > gr1 ? -1.0e12f : 0.0f);
        }

        float tm0 = -3.0e38f, tm1 = -3.0e38f;
        #pragma unroll
        for (int nf = 0; nf < 16; nf++) {
            tm0 = fmaxf(tm0, fmaxf(sacc[nf][0], sacc[nf][1]));
            tm1 = fmaxf(tm1, fmaxf(sacc[nf][2], sacc[nf][3]));
        }
        tm0 = fmaxf(tm0, __shfl_xor_sync(0xffffffffu, tm0, 1));
        tm0 = fmaxf(tm0, __shfl_xor_sync(0xffffffffu, tm0, 2));
        tm1 = fmaxf(tm1, __shfl_xor_sync(0xffffffffu, tm1, 1));
        tm1 = fmaxf(tm1, __shfl_xor_sync(0xffffffffu, tm1, 2));
        const float mn0 = fmaxf(m0r, tm0), mn1 = fmaxf(m1r, tm1);
        const float sc0 = __expf(m0r - mn0), sc1 = __expf(m1r - mn1);
        float ls0 = 0.0f, ls1 = 0.0f;
        #pragma unroll
        for (int nf = 0; nf < 16; nf++) {
            sacc[nf][0] = __expf(sacc[nf][0] - mn0); ls0 += sacc[nf][0];
            sacc[nf][1] = __expf(sacc[nf][1] - mn0); ls0 += sacc[nf][1];
            sacc[nf][2] = __expf(sacc[nf][2] - mn1); ls1 += sacc[nf][2];
            sacc[nf][3] = __expf(sacc[nf][3] - mn1); ls1 += sacc[nf][3];
        }
        ls0 += __shfl_xor_sync(0xffffffffu, ls0, 1);
        ls0 += __shfl_xor_sync(0xffffffffu, ls0, 2);
        ls1 += __shfl_xor_sync(0xffffffffu, ls1, 1);
        ls1 += __shfl_xor_sync(0xffffffffu, ls1, 2);
        l0r = l0r * sc0 + ls0;  l1r = l1r * sc1 + ls1;
        m0r = mn0;  m1r = mn1;
        #pragma unroll
        for (int nf = 0; nf < 8; nf++) {
            oacc[nf][0] *= sc0; oacc[nf][1] *= sc0;
            oacc[nf][2] *= sc1; oacc[nf][3] *= sc1;
        }

        const uint32_t vtb = vhb +
            (uint32_t)(((lane >> 3) & 1) * 8 + (lane & 7)) * (SST * 2) +
            (lane >> 4) * 16;
        #pragma unroll
        for (int kc = 0; kc < 8; kc++) {
            uint32_t AH[4], AL[4];
            #pragma unroll
            for (int half = 0; half < 2; half++) {
                const float* sp = sacc[2 * kc + half];
                uint32_t h0 = packbf2(sp[0], sp[1]);
                uint32_t h1 = packbf2(sp[2], sp[3]);
                AH[2 * half + 0] = h0;  AH[2 * half + 1] = h1;
                __nv_bfloat162 hv0 = *(__nv_bfloat162*)&h0;
                __nv_bfloat162 hv1 = *(__nv_bfloat162*)&h1;
                AL[2 * half + 0] = packbf2(sp[0] - __bfloat162float(hv0.x),
                                           sp[1] - __bfloat162float(hv0.y));
                AL[2 * half + 1] = packbf2(sp[2] - __bfloat162float(hv1.x),
                                           sp[3] - __bfloat162float(hv1.y));
            }
            const uint32_t vrow = vtb + (uint32_t)(kc * 16) * (SST * 2);
            #pragma unroll
            for (int nfp = 0; nfp < 4; nfp++) {
                uint32_t r0, r1, r2, r3;
                ldsm4t(r0, r1, r2, r3, vrow + nfp * 32);
                mma16816(oacc[2 * nfp],     AH, r0, r1);
                mma16816(oacc[2 * nfp + 1], AH, r2, r3);
                mma16816(oacc[2 * nfp],     AL, r0, r1);
                mma16816(oacc[2 * nfp + 1], AL, r2, r3);
                uint32_t c0, c1, c2, c3;
                ldsm4t(c0, c1, c2, c3, vrow + STB + nfp * 32);
                mma16816(oacc[2 * nfp],     AH, c0, c1);
                mma16816(oacc[2 * nfp + 1], AH, c2, c3);
            }
        }
    }

    const float inv0 = 1.0f / l0r, inv1 = 1.0f / l1r;
    const int r0g = qrow0 + wid * 16 + g, r1g = r0g + 8;
    const size_t o0 = ((size_t)(b * 1024 + r0g)) * 1024 + headoff;
    const size_t o1 = ((size_t)(b * 1024 + r1g)) * 1024 + headoff;
    #pragma unroll
    for (int nf = 0; nf < 8; nf++) {
        int c = nf * 8 + tg * 2;
        float x = oacc[nf][0] * inv0, y = oacc[nf][1] * inv0;
        __nv_bfloat16 hx = __float2bfloat16(x), hy = __float2bfloat16(y);
        *(__nv_bfloat162*)(g_ah + o0 + c) = __nv_bfloat162(hx, hy);
        *(__nv_bfloat162*)(g_al + o0 + c) = __nv_bfloat162(
            __float2bfloat16(x - __bfloat162float(hx)),
            __float2bfloat16(y - __bfloat162float(hy)));
        x = oacc[nf][2] * inv1; y = oacc[nf][3] * inv1;
        hx = __float2bfloat16(x); hy = __float2bfloat16(y);
        *(__nv_bfloat162*)(g_ah + o1 + c) = __nv_bfloat162(hx, hy);
        *(__nv_bfloat162*)(g_al + o1 + c) = __nv_bfloat162(
            __float2bfloat16(x - __bfloat162float(hx)),
            __float2bfloat16(y - __bfloat162float(hy)));
    }
}

// ==================== degenerate-row fixup (parallel, exact) ================
__global__ void attn_fixup(const int* __restrict__ vmask)
{
    const int b = blockIdx.x, dc = blockIdx.y;
    const int tid = threadIdx.x;
    const int d = tid & 63, jl = tid >> 6;
    __shared__ int sL, scnt;
    __shared__ float part[4][64];
    if (tid == 0) { sL = 1024; scnt = 0; }
    __syncthreads();

    int local = 1024, c = 0;
    for (int j = tid; j < 1024; j += 256) {
        int mk = vmask[b * 1024 + j];
        if (mk) local = min(local, j);
        c += mk;
    }
    atomicMin(&sL, local);
    atomicAdd(&scnt, c);
    __syncthreads();
    const int L = sL;
    if (L == 0) return;

    const int dim = dc * 64 + d;
    float t = 0.f;
    for (int j = jl; j < 1024; j += 4) {
        if (vmask[b * 1024 + j]) {
            size_t off = ((size_t)(b * 1024 + j)) * 1024 + dim;
            t += __bfloat162float(g_vh[off]) + __bfloat162float(g_vl[off]);
        }
    }
    part[jl][d] = t;
    __syncthreads();

    if (jl == 0) {
        float T = part[0][d] + part[1][d] + part[2][d] + part[3][d];
        const int cnt = scnt;
        float P = 0.f;
        for (int r = 0; r < L; r++) {
            size_t off = ((size_t)(b * 1024 + r)) * 1024 + dim;
            P += __bfloat162float(g_vh[off]) + __bfloat162float(g_vl[off]);
            float o = (P + T) / (float)(r + 1 + cnt);
            __nv_bfloat16 hh = __float2bfloat16(o);
            g_ah[off] = hh;
            g_al[off] = __float2bfloat16(o - __bfloat162float(hh));
        }
    }
}

// ==================== launch ====================
extern "C" void kernel_launch(void* const* d_in, const int* in_sizes, int n_in,
                              void* d_out, int out_size)
{
    const float* q     = (const float*)d_in[0];
    const float* k     = (const float*)d_in[1];
    const float* v     = (const float*)d_in[2];
    const int*   vmask = (const int*)d_in[3];
    const int*   qmask = (const int*)d_in[4];
    const float* Wq = (const float*)d_in[6];
    const float* bq = (const float*)d_in[7];
    const float* Wk = (const float*)d_in[8];
    const float* bk = (const float*)d_in[9];
    const float* Wv = (const float*)d_in[10];
    const float* bv = (const float*)d_in[11];
    const float* Wo = (const float*)d_in[12];
    const float* bo = (const float*)d_in[13];
    float* out = (float*)d_out;

    const int N4 = 4194304 / 4;
    conv_split3<<<dim3(N4 / 256, 1, 3), 256>>>(q, k, v, N4);
    convT_split4<<<dim3(32, 32, 4), dim3(32, 8)>>>(Wq, Wk, Wv, Wo);

    const int GEMM_SMEM = N_STAGE * STAGE_B;   // 122,880 B
    cudaFuncSetAttribute(tc_gemm_qkv,
                         cudaFuncAttributeMaxDynamicSharedMemorySize, GEMM_SMEM);
    cudaFuncSetAttribute(tc_gemm_final,
                         cudaFuncAttributeMaxDynamicSharedMemorySize, GEMM_SMEM);
    tc_gemm_qkv<<<dim3(8, 32, 3), 256, GEMM_SMEM>>>(bq, bk, bv);

    const int ATTN_SMEM = 8 * STB + 2 * 128 * (int)sizeof(float);  // 148,480 B
    cudaFuncSetAttribute(attn_tc,
                         cudaFuncAttributeMaxDynamicSharedMemorySize, ATTN_SMEM);
    attn_tc<<<512, 256, ATTN_SMEM>>>(vmask);
    attn_fixup<<<dim3(4, 16), 256>>>(vmask);

    tc_gemm_final<<<dim3(8, 32), 256, GEMM_SMEM>>>(bo, qmask, out);
}

// round 17
// speedup vs baseline: 1.0828x; 1.0828x over previous
#include <cuda_runtime.h>
#include <cuda_bf16.h>
#include <cstdint>

// ==================== scratch (no cudaMalloc allowed) ====================
__device__ __nv_bfloat16 g_xqh[4194304], g_xql[4194304];
__device__ __nv_bfloat16 g_xkh[4194304], g_xkl[4194304];
__device__ __nv_bfloat16 g_xvh[4194304], g_xvl[4194304];
__device__ __nv_bfloat16 g_wqh[1048576], g_wql[1048576];
__device__ __nv_bfloat16 g_wkh[1048576], g_wkl[1048576];
__device__ __nv_bfloat16 g_wvh[1048576], g_wvl[1048576];
__device__ __nv_bfloat16 g_woh[1048576], g_wol[1048576];
__device__ __nv_bfloat16 g_qh[4194304], g_ql[4194304];
__device__ __nv_bfloat16 g_kh[4194304], g_kl[4194304];
__device__ __nv_bfloat16 g_vh[4194304], g_vl[4194304];
__device__ __nv_bfloat16 g_ah[4194304], g_al[4194304];

// ==================== helpers ====================
__device__ __forceinline__ uint32_t smem_u32(const void* p) {
    uint32_t a;
    asm("{ .reg .u64 t; cvta.to.shared.u64 t, %1; cvt.u32.u64 %0, t; }"
        : "=r"(a) : "l"(p));
    return a;
}
__device__ __forceinline__ void cp16(uint32_t s, const void* g) {
    asm volatile("cp.async.cg.shared.global [%0], [%1], 16;" :: "r"(s), "l"(g));
}
#define CP_COMMIT() asm volatile("cp.async.commit_group;" ::: "memory")

__device__ __forceinline__ void ldsm4(uint32_t& r0, uint32_t& r1,
                                      uint32_t& r2, uint32_t& r3, uint32_t a) {
    asm volatile("ldmatrix.sync.aligned.m8n8.x4.shared.b16 {%0,%1,%2,%3}, [%4];"
                 : "=r"(r0), "=r"(r1), "=r"(r2), "=r"(r3) : "r"(a));
}
__device__ __forceinline__ void ldsm4t(uint32_t& r0, uint32_t& r1,
                                       uint32_t& r2, uint32_t& r3, uint32_t a) {
    asm volatile("ldmatrix.sync.aligned.m8n8.x4.trans.shared.b16 {%0,%1,%2,%3}, [%4];"
                 : "=r"(r0), "=r"(r1), "=r"(r2), "=r"(r3) : "r"(a));
}
__device__ __forceinline__ void mma16816(float* d, const uint32_t* a,
                                         uint32_t b0, uint32_t b1) {
    asm volatile("mma.sync.aligned.m16n8k16.row.col.f32.bf16.bf16.f32 "
                 "{%0,%1,%2,%3}, {%4,%5,%6,%7}, {%8,%9}, {%0,%1,%2,%3};"
                 : "+f"(d[0]), "+f"(d[1]), "+f"(d[2]), "+f"(d[3])
                 : "r"(a[0]), "r"(a[1]), "r"(a[2]), "r"(a[3]), "r"(b0), "r"(b1));
}
__device__ __forceinline__ uint32_t packbf2(float x0, float x1) {
    uint32_t r;
    asm("cvt.rn.bf16x2.f32 %0, %1, %2;" : "=r"(r) : "f"(x1), "f"(x0));
    return r;
}

// ==================== fp32 -> (hi, lo) bf16 split, wide stores ====
// 8 floats/thread: 2x LDG.128 in, 1x STG.128 to hi + 1x STG.128 to lo.
// Same per-element arithmetic as before (bit-identical results); only the
// thread mapping / store width changed to cut STG issue cost ~2.5x.
__global__ void conv_split3(const float* __restrict__ q,
                            const float* __restrict__ k,
                            const float* __restrict__ v, int n8) {
    int i = blockIdx.x * blockDim.x + threadIdx.x;
    if (i >= n8) return;
    const int z = blockIdx.z;
    const float* in = (z == 0) ? q : (z == 1) ? k : v;
    __nv_bfloat16* hi = (z == 0) ? g_xqh : (z == 1) ? g_xkh : g_xvh;
    __nv_bfloat16* lo = (z == 0) ? g_xql : (z == 1) ? g_xkl : g_xvl;
    float4 a = ((const float4*)in)[2 * i];
    float4 c = ((const float4*)in)[2 * i + 1];
    __nv_bfloat162 h[4], l[4];
    __nv_bfloat16 h0 = __float2bfloat16(a.x), h1 = __float2bfloat16(a.y);
    __nv_bfloat16 h2 = __float2bfloat16(a.z), h3 = __float2bfloat16(a.w);
    __nv_bfloat16 h4 = __float2bfloat16(c.x), h5 = __float2bfloat16(c.y);
    __nv_bfloat16 h6 = __float2bfloat16(c.z), h7 = __float2bfloat16(c.w);
    h[0] = __nv_bfloat162(h0, h1); h[1] = __nv_bfloat162(h2, h3);
    h[2] = __nv_bfloat162(h4, h5); h[3] = __nv_bfloat162(h6, h7);
    l[0] = __nv_bfloat162(__float2bfloat16(a.x - __bfloat162float(h0)),
                          __float2bfloat16(a.y - __bfloat162float(h1)));
    l[1] = __nv_bfloat162(__float2bfloat16(a.z - __bfloat162float(h2)),
                          __float2bfloat16(a.w - __bfloat162float(h3)));
    l[2] = __nv_bfloat162(__float2bfloat16(c.x - __bfloat162float(h4)),
                          __float2bfloat16(c.y - __bfloat162float(h5)));
    l[3] = __nv_bfloat162(__float2bfloat16(c.z - __bfloat162float(h6)),
                          __float2bfloat16(c.w - __bfloat162float(h7)));
    *(uint4*)(hi + 8 * (size_t)i) = *(uint4*)h;
    *(uint4*)(lo + 8 * (size_t)i) = *(uint4*)l;
}

__global__ void convT_split4(const float* __restrict__ Wq,
                             const float* __restrict__ Wk,
                             const float* __restrict__ Wv,
                             const float* __restrict__ Wo) {
    __shared__ float t[32][33];
    const int z = blockIdx.z;
    const float* W = (z == 0) ? Wq : (z == 1) ? Wk : (z == 2) ? Wv : Wo;
    __nv_bfloat16* hi = (z == 0) ? g_wqh : (z == 1) ? g_wkh : (z == 2) ? g_wvh : g_woh;
    __nv_bfloat16* lo = (z == 0) ? g_wql : (z == 1) ? g_wkl : (z == 2) ? g_wvl : g_wol;
    int n0 = blockIdx.x * 32, k0 = blockIdx.y * 32;
    int tx = threadIdx.x, ty = threadIdx.y;
    #pragma unroll
    for (int i = 0; i < 4; i++)
        t[ty + 8 * i][tx] = W[(size_t)(k0 + ty + 8 * i) * 1024 + n0 + tx];
    __syncthreads();
    #pragma unroll
    for (int i = 0; i < 4; i++) {
        float a = t[tx][ty + 8 * i];
        __nv_bfloat16 h = __float2bfloat16(a);
        size_t o = (size_t)(n0 + ty + 8 * i) * 1024 + k0 + tx;
        hi[o] = h;
        lo[o] = __float2bfloat16(a - __bfloat162float(h));
    }
}

// ==================== GEMM mainloop (R15-proven: 2-stage, occ 2) ============
// Three structural experiments (R7 hoist, R12 merge-only, R16 3-stage/occ1)
// all failed to beat this; occ-1 costing only ~10% proves HMMA-pipe-bound.
// DO NOT restructure.
#define TILE_B   10240               // 128 * 80
#define STAGE_B  40960               // 4 tiles

#define GEMM_MAINLOOP()                                                        \
    const int frow = ((lane >> 3) & 1) * 8 + (lane & 7);                       \
    const int fchk = lane >> 4;                                                \
    const uint32_t aoff = (uint32_t)((warp_m * 32 + frow) * 80 + fchk * 16);   \
    const uint32_t boff = (uint32_t)((warp_n * 64 + frow) * 80 + fchk * 16);   \
    const int r_ld = tid >> 2, c_ld = tid & 3;                                 \
    float acc[2][8][4];                                                        \
    _Pragma("unroll")                                                          \
    for (int mf = 0; mf < 2; mf++)                                             \
        _Pragma("unroll")                                                      \
        for (int nf = 0; nf < 8; nf++)                                         \
            _Pragma("unroll")                                                  \
            for (int e = 0; e < 4; e++) acc[mf][nf][e] = 0.0f;                 \
    _Pragma("unroll")                                                          \
    for (int t = 0; t < 4; t++)                                                \
        _Pragma("unroll")                                                      \
        for (int i = 0; i < 2; i++) {                                          \
            int r = r_ld + i * 64;                                             \
            cp16(sb + t * TILE_B + r * 80 + c_ld * 16,                         \
                 srcs[t] + (size_t)r * 1024 + c_ld * 8);                       \
        }                                                                      \
    CP_COMMIT();                                                               \
    for (int ch = 0; ch < 32; ch++) {                                          \
        if (ch + 1 < 32) {                                                     \
            const uint32_t dst = sb + ((ch + 1) & 1) * STAGE_B;                \
            const int k0 = (ch + 1) * 32;                                      \
            _Pragma("unroll")                                                  \
            for (int t = 0; t < 4; t++)                                        \
                _Pragma("unroll")                                              \
                for (int i = 0; i < 2; i++) {                                  \
                    int r = r_ld + i * 64;                                     \
                    cp16(dst + t * TILE_B + r * 80 + c_ld * 16,                \
                         srcs[t] + (size_t)r * 1024 + k0 + c_ld * 8);          \
                }                                                              \
            CP_COMMIT();                                                       \
            asm volatile("cp.async.wait_group 1;" ::: "memory");               \
        } else {                                                               \
            asm volatile("cp.async.wait_group 0;" ::: "memory");               \
        }                                                                      \
        __syncthreads();                                                       \
        const uint32_t stage = sb + (ch & 1) * STAGE_B;                        \
        _Pragma("unroll")                                                      \
        for (int term = 0; term < 3; term++) {                                 \
            const uint32_t sA = stage + (term == 2 ? TILE_B : 0u);             \
            const uint32_t sB = stage + 2u * TILE_B + (term == 1 ? TILE_B : 0u); \
            _Pragma("unroll")                                                  \
            for (int ks = 0; ks < 2; ks++) {                                   \
                uint32_t a[2][4];                                              \
                ldsm4(a[0][0], a[0][1], a[0][2], a[0][3], sA + aoff + ks * 32);\
                ldsm4(a[1][0], a[1][1], a[1][2], a[1][3],                      \
                      sA + aoff + 1280 + ks * 32);                             \
                uint32_t b[4][4];                                              \
                _Pragma("unroll")                                              \
                for (int nfp = 0; nfp < 4; nfp++)                              \
                    ldsm4(b[nfp][0], b[nfp][1], b[nfp][2], b[nfp][3],          \
                          sB + boff + nfp * 1280 + ks * 32);                   \
                _Pragma("unroll")                                              \
                for (int mf = 0; mf < 2; mf++)                                 \
                    _Pragma("unroll")                                          \
                    for (int nfp = 0; nfp < 4; nfp++) {                        \
                        mma16816(acc[mf][2 * nfp],     a[mf], b[nfp][0], b[nfp][2]); \
                        mma16816(acc[mf][2 * nfp + 1], a[mf], b[nfp][1], b[nfp][3]); \
                    }                                                          \
            }                                                                  \
        }                                                                      \
        __syncthreads();                                                       \
    }

// QKV projections, merged via grid.z. Split-bf16 epilogue.
__global__ void __launch_bounds__(256, 2) tc_gemm_qkv(
    const float* __restrict__ bq, const float* __restrict__ bk,
    const float* __restrict__ bv)
{
    extern __shared__ char smem[];
    const uint32_t sb = smem_u32(smem);
    const int tid = threadIdx.x, wid = tid >> 5, lane = tid & 31;
    const int m0 = blockIdx.y * 128, n0 = blockIdx.x * 128;
    const int warp_m = wid & 3, warp_n = wid >> 2;
    const int z = blockIdx.z;

    const __nv_bfloat16* Ah = (z == 0) ? g_xqh : (z == 1) ? g_xkh : g_xvh;
    const __nv_bfloat16* Al = (z == 0) ? g_xql : (z == 1) ? g_xkl : g_xvl;
    const __nv_bfloat16* Bh = (z == 0) ? g_wqh : (z == 1) ? g_wkh : g_wvh;
    const __nv_bfloat16* Bl = (z == 0) ? g_wql : (z == 1) ? g_wkl : g_wvl;
    const float* bias       = (z == 0) ? bq    : (z == 1) ? bk    : bv;
    __nv_bfloat16* Ch       = (z == 0) ? g_qh  : (z == 1) ? g_kh  : g_vh;
    __nv_bfloat16* Cl       = (z == 0) ? g_ql  : (z == 1) ? g_kl  : g_vl;

    const __nv_bfloat16* srcs[4] = {
        Ah + (size_t)m0 * 1024, Al + (size_t)m0 * 1024,
        Bh + (size_t)n0 * 1024, Bl + (size_t)n0 * 1024 };

    GEMM_MAINLOOP()

    const int rbase = m0 + warp_m * 32 + (lane >> 2);
    const int cbase = n0 + warp_n * 64 + (lane & 3) * 2;
    #pragma unroll
    for (int mf = 0; mf < 2; mf++)
        #pragma unroll
        for (int h = 0; h < 2; h++) {
            int r = rbase + mf * 16 + h * 8;
            #pragma unroll
            for (int nf = 0; nf < 8; nf++) {
                int cc = cbase + nf * 8;
                float x = acc[mf][nf][2 * h + 0] + bias[cc];
                float y = acc[mf][nf][2 * h + 1] + bias[cc + 1];
                __nv_bfloat16 hx = __float2bfloat16(x);
                __nv_bfloat16 hy = __float2bfloat16(y);
                *(__nv_bfloat162*)(Ch + (size_t)r * 1024 + cc) = __nv_bfloat162(hx, hy);
                *(__nv_bfloat162*)(Cl + (size_t)r * 1024 + cc) = __nv_bfloat162(
                    __float2bfloat16(x - __bfloat162float(hx)),
                    __float2bfloat16(y - __bfloat162float(hy)));
            }
        }
}

// Final projection: fp32 out * qmask.
__global__ void __launch_bounds__(256, 2) tc_gemm_final(
    const float* __restrict__ bias, const int* __restrict__ qmask,
    float* __restrict__ C)
{
    extern __shared__ char smem[];
    const uint32_t sb = smem_u32(smem);
    const int tid = threadIdx.x, wid = tid >> 5, lane = tid & 31;
    const int m0 = blockIdx.y * 128, n0 = blockIdx.x * 128;
    const int warp_m = wid & 3, warp_n = wid >> 2;

    const __nv_bfloat16* srcs[4] = {
        g_ah + (size_t)m0 * 1024, g_al + (size_t)m0 * 1024,
        g_woh + (size_t)n0 * 1024, g_wol + (size_t)n0 * 1024 };

    GEMM_MAINLOOP()

    const int rbase = m0 + warp_m * 32 + (lane >> 2);
    const int cbase = n0 + warp_n * 64 + (lane & 3) * 2;
    #pragma unroll
    for (int mf = 0; mf < 2; mf++)
        #pragma unroll
        for (int h = 0; h < 2; h++) {
            int r = rbase + mf * 16 + h * 8;
            float qm = (float)qmask[r];
            #pragma unroll
            for (int nf = 0; nf < 8; nf++) {
                int cc = cbase + nf * 8;
                float2 o;
                o.x = (acc[mf][nf][2 * h + 0] + bias[cc])     * qm;
                o.y = (acc[mf][nf][2 * h + 1] + bias[cc + 1]) * qm;
                *(float2*)(C + (size_t)r * 1024 + cc) = o;
            }
        }
}

// ==================== tensor-core flash attention (R15, 97.4us, unchanged) ===
#define SST 72
#define STB (128 * SST * 2)          // 18432 B per tile

#define LOAD_KV(JT, S) do {                                                   \
    const int kv0_ = (JT) * 128;                                              \
    const __nv_bfloat16* mats_[4] = {                                         \
        g_kh + ((size_t)(b * 1024 + kv0_)) * 1024 + headoff,                  \
        g_kl + ((size_t)(b * 1024 + kv0_)) * 1024 + headoff,                  \
        g_vh + ((size_t)(b * 1024 + kv0_)) * 1024 + headoff,                  \
        g_vl + ((size_t)(b * 1024 + kv0_)) * 1024 + headoff };                \
    uint32_t base_ = sb + (S) * 4 * STB;                                      \
    _Pragma("unroll")                                                         \
    for (int m_ = 0; m_ < 4; m_++)                                            \
        _Pragma("unroll")                                                     \
        for (int i_ = 0; i_ < 4; i_++) {                                      \
            int idx_ = tid + i_ * 256;                                        \
            int r_ = idx_ >> 3, ch_ = idx_ & 7;                               \
            cp16(base_ + m_ * STB + r_ * (SST * 2) + ch_ * 16,                \
                 mats_[m_] + (size_t)r_ * 1024 + ch_ * 8);                    \
        }                                                                     \
    if (tid < 128)                                                            \
        vmadd[(S) * 128 + tid] =                                              \
            vmask[b * 1024 + kv0_ + tid] ? 0.0f : -1.0e12f;                   \
    CP_COMMIT();                                                              \
} while (0)

__global__ void __launch_bounds__(256, 1) attn_tc(const int* __restrict__ vmask)
{
    extern __shared__ char smem[];
    const uint32_t sb = smem_u32(smem);
    float* vmadd = (float*)(smem + 8 * STB);   // [2][128]

    const int bid = blockIdx.x;                // 0..511, LPT: heavy first
    const int it = 7 - (bid >> 6);
    const int bh = bid & 63;
    const int b = bh >> 4, h = bh & 15;
    const int tid = threadIdx.x, wid = tid >> 5, lane = tid & 31;
    const int g = lane >> 2, tg = lane & 3;
    const size_t headoff = (size_t)h * 64;
    const int qrow0 = it * 128;
    const int frow = lane & 15, fchk = lane >> 4;
    const int nt = it + 1;                     // causal: tiles 0..it only

    #pragma unroll
    for (int m = 0; m < 2; m++) {
        const __nv_bfloat16* src =
            (m ? g_ql : g_qh) + ((size_t)(b * 1024 + qrow0)) * 1024 + headoff;
        uint32_t dstb = sb + m * STB;
        #pragma unroll
        for (int i = 0; i < 4; i++) {
            int idx = tid + i * 256;
            int r = idx >> 3, ch = idx & 7;
            cp16(dstb + r * (SST * 2) + ch * 16, src + (size_t)r * 1024 + ch * 8);
        }
    }
    CP_COMMIT();
    asm volatile("cp.async.wait_group 0;" ::: "memory");
    __syncthreads();

    uint32_t qfh[4][4], qfl[4][4];
    {
        uint32_t abase = sb + (wid * 16 + frow) * (SST * 2) + fchk * 16;
        #pragma unroll
        for (int ks = 0; ks < 4; ks++) {
            ldsm4(qfh[ks][0], qfh[ks][1], qfh[ks][2], qfh[ks][3], abase + ks * 32);
            ldsm4(qfl[ks][0], qfl[ks][1], qfl[ks][2], qfl[ks][3],
                  abase + STB + ks * 32);
        }
    }
    __syncthreads();

    float oacc[8][4];
    #pragma unroll
    for (int nf = 0; nf < 8; nf++)
        #pragma unroll
        for (int e = 0; e < 4; e++) oacc[nf][e] = 0.0f;
    float m0r = -3.0e38f, m1r = -3.0e38f, l0r = 0.0f, l1r = 0.0f;

    LOAD_KV(0, 0);

    for (int jt = 0; jt < nt; jt++) {
        if (jt > 0) __syncthreads();
        if (jt + 1 < nt) {
            LOAD_KV(jt + 1, (jt + 1) & 1);
            asm volatile("cp.async.wait_group 1;" ::: "memory");
        } else {
            asm volatile("cp.async.wait_group 0;" ::: "memory");
        }
        __syncthreads();

        const int s = jt & 1;
        const int kv0 = jt * 128;
        const float* vm_s = vmadd + s * 128;
        const uint32_t khb = sb + s * 4 * STB;
        const uint32_t vhb = khb + 2 * STB;

        float sacc[16][4];
        #pragma unroll
        for (int nf = 0; nf < 16; nf++)
            #pragma unroll
            for (int e = 0; e < 4; e++) sacc[nf][e] = 0.0f;

        const uint32_t kaddr = khb + frow * (SST * 2) + fchk * 16;
        #pragma unroll
        for (int ks = 0; ks < 4; ks++)
            #pragma unroll
            for (int nfp = 0; nfp < 8; nfp++) {
                uint32_t off = (uint32_t)(nfp * 16) * (SST * 2) + ks * 32;
                uint32_t b0, b1, b2, b3;
                ldsm4(b0, b1, b2, b3, kaddr + off);
                mma16816(sacc[2 * nfp],     qfh[ks], b0, b2);
                mma16816(sacc[2 * nfp + 1], qfh[ks], b1, b3);
                mma16816(sacc[2 * nfp],     qfl[ks], b0, b2);
                mma16816(sacc[2 * nfp + 1], qfl[ks], b1, b3);
                uint32_t c0, c1, c2, c3;
                ldsm4(c0, c1, c2, c3, kaddr + off + STB);
                mma16816(sacc[2 * nfp],     qfh[ks], c0, c2);
                mma16816(sacc[2 * nfp + 1], qfh[ks], c1, c3);
            }

        const int gr0 = qrow0 + wid * 16 + g, gr1 = gr0 + 8;
        #pragma unroll
        for (int nf = 0; nf < 16; nf++) {
            int c0 = nf * 8 + tg * 2;
            int gc0 = kv0 + c0, gc1 = gc0 + 1;
            float vm0 = vm_s[c0], vm1 = vm_s[c0 + 1];
            sacc[nf][0] = sacc[nf][0] * 0.125f + vm0 + (gc0 > gr0 ? -1.0e12f : 0.0f);
            sacc[nf][1] = sacc[nf][1] * 0.125f + vm1 + (gc1 > gr0 ? -1.0e12f : 0.0f);
            sacc[nf][2] = sacc[nf][2] * 0.125f + vm0 + (gc0 > gr1 ? -1.0e12f : 0.0f);
            sacc[nf][3] = sacc[nf][3] * 0.125f + vm1 + (gc1 > gr1 ? -1.0e12f : 0.0f);
        }

        float tm0 = -3.0e38f, tm1 = -3.0e38f;
        #pragma unroll
        for (int nf = 0; nf < 16; nf++) {
            tm0 = fmaxf(tm0, fmaxf(sacc[nf][0], sacc[nf][1]));
            tm1 = fmaxf(tm1, fmaxf(sacc[nf][2], sacc[nf][3]));
        }
        tm0 = fmaxf(tm0, __shfl_xor_sync(0xffffffffu, tm0, 1));
        tm0 = fmaxf(tm0, __shfl_xor_sync(0xffffffffu, tm0, 2));
        tm1 = fmaxf(tm1, __shfl_xor_sync(0xffffffffu, tm1, 1));
        tm1 = fmaxf(tm1, __shfl_xor_sync(0xffffffffu, tm1, 2));
        const float mn0 = fmaxf(m0r, tm0), mn1 = fmaxf(m1r, tm1);
        const float sc0 = __expf(m0r - mn0), sc1 = __expf(m1r - mn1);
        float ls0 = 0.0f, ls1 = 0.0f;
        #pragma unroll
        for (int nf = 0; nf < 16; nf++) {
            sacc[nf][0] = __expf(sacc[nf][0] - mn0); ls0 += sacc[nf][0];
            sacc[nf][1] = __expf(sacc[nf][1] - mn0); ls0 += sacc[nf][1];
            sacc[nf][2] = __expf(sacc[nf][2] - mn1); ls1 += sacc[nf][2];
            sacc[nf][3] = __expf(sacc[nf][3] - mn1); ls1 += sacc[nf][3];
        }
        ls0 += __shfl_xor_sync(0xffffffffu, ls0, 1);
        ls0 += __shfl_xor_sync(0xffffffffu, ls0, 2);
        ls1 += __shfl_xor_sync(0xffffffffu, ls1, 1);
        ls1 += __shfl_xor_sync(0xffffffffu, ls1, 2);
        l0r = l0r * sc0 + ls0;  l1r = l1r * sc1 + ls1;
        m0r = mn0;  m1r = mn1;
        #pragma unroll
        for (int nf = 0; nf < 8; nf++) {
            oacc[nf][0] *= sc0; oacc[nf][1] *= sc0;
            oacc[nf][2] *= sc1; oacc[nf][3] *= sc1;
        }

        const uint32_t vtb = vhb +
            (uint32_t)(((lane >> 3) & 1) * 8 + (lane & 7)) * (SST * 2) +
            (lane >> 4) * 16;
        #pragma unroll
        for (int kc = 0; kc < 8; kc++) {
            uint32_t AH[4], AL[4];
            #pragma unroll
            for (int half = 0; half < 2; half++) {
                const float* sp = sacc[2 * kc + half];
                uint32_t h0 = packbf2(sp[0], sp[1]);
                uint32_t h1 = packbf2(sp[2], sp[3]);
                AH[2 * half + 0] = h0;  AH[2 * half + 1] = h1;
                __nv_bfloat162 hv0 = *(__nv_bfloat162*)&h0;
                __nv_bfloat162 hv1 = *(__nv_bfloat162*)&h1;
                AL[2 * half + 0] = packbf2(sp[0] - __bfloat162float(hv0.x),
                                           sp[1] - __bfloat162float(hv0.y));
                AL[2 * half + 1] = packbf2(sp[2] - __bfloat162float(hv1.x),
                                           sp[3] - __bfloat162float(hv1.y));
            }
            const uint32_t vrow = vtb + (uint32_t)(kc * 16) * (SST * 2);
            #pragma unroll
            for (int nfp = 0; nfp < 4; nfp++) {
                uint32_t r0, r1, r2, r3;
                ldsm4t(r0, r1, r2, r3, vrow + nfp * 32);
                mma16816(oacc[2 * nfp],     AH, r0, r1);
                mma16816(oacc[2 * nfp + 1], AH, r2, r3);
                mma16816(oacc[2 * nfp],     AL, r0, r1);
                mma16816(oacc[2 * nfp + 1], AL, r2, r3);
                uint32_t c0, c1, c2, c3;
                ldsm4t(c0, c1, c2, c3, vrow + STB + nfp * 32);
                mma16816(oacc[2 * nfp],     AH, c0, c1);
                mma16816(oacc[2 * nfp + 1], AH, c2, c3);
            }
        }
    }

    const float inv0 = 1.0f / l0r, inv1 = 1.0f / l1r;
    const int r0g = qrow0 + wid * 16 + g, r1g = r0g + 8;
    const size_t o0 = ((size_t)(b * 1024 + r0g)) * 1024 + headoff;
    const size_t o1 = ((size_t)(b * 1024 + r1g)) * 1024 + headoff;
    #pragma unroll
    for (int nf = 0; nf < 8; nf++) {
        int c = nf * 8 + tg * 2;
        float x = oacc[nf][0] * inv0, y = oacc[nf][1] * inv0;
        __nv_bfloat16 hx = __float2bfloat16(x), hy = __float2bfloat16(y);
        *(__nv_bfloat162*)(g_ah + o0 + c) = __nv_bfloat162(hx, hy);
        *(__nv_bfloat162*)(g_al + o0 + c) = __nv_bfloat162(
            __float2bfloat16(x - __bfloat162float(hx)),
            __float2bfloat16(y - __bfloat162float(hy)));
        x = oacc[nf][2] * inv1; y = oacc[nf][3] * inv1;
        hx = __float2bfloat16(x); hy = __float2bfloat16(y);
        *(__nv_bfloat162*)(g_ah + o1 + c) = __nv_bfloat162(hx, hy);
        *(__nv_bfloat162*)(g_al + o1 + c) = __nv_bfloat162(
            __float2bfloat16(x - __bfloat162float(hx)),
            __float2bfloat16(y - __bfloat162float(hy)));
    }
}

// ==================== degenerate-row fixup (parallel, exact) ================
__global__ void attn_fixup(const int* __restrict__ vmask)
{
    const int b = blockIdx.x, dc = blockIdx.y;
    const int tid = threadIdx.x;
    const int d = tid & 63, jl = tid >> 6;
    __shared__ int sL, scnt;
    __shared__ float part[4][64];
    if (tid == 0) { sL = 1024; scnt = 0; }
    __syncthreads();

    int local = 1024, c = 0;
    for (int j = tid; j < 1024; j += 256) {
        int mk = vmask[b * 1024 + j];
        if (mk) local = min(local, j);
        c += mk;
    }
    atomicMin(&sL, local);
    atomicAdd(&scnt, c);
    __syncthreads();
    const int L = sL;
    if (L == 0) return;

    const int dim = dc * 64 + d;
    float t = 0.f;
    for (int j = jl; j < 1024; j += 4) {
        if (vmask[b * 1024 + j]) {
            size_t off = ((size_t)(b * 1024 + j)) * 1024 + dim;
            t += __bfloat162float(g_vh[off]) + __bfloat162float(g_vl[off]);
        }
    }
    part[jl][d] = t;
    __syncthreads();

    if (jl == 0) {
        float T = part[0][d] + part[1][d] + part[2][d] + part[3][d];
        const int cnt = scnt;
        float P = 0.f;
        for (int r = 0; r < L; r++) {
            size_t off = ((size_t)(b * 1024 + r)) * 1024 + dim;
            P += __bfloat162float(g_vh[off]) + __bfloat162float(g_vl[off]);
            float o = (P + T) / (float)(r + 1 + cnt);
            __nv_bfloat16 hh = __float2bfloat16(o);
            g_ah[off] = hh;
            g_al[off] = __float2bfloat16(o - __bfloat162float(hh));
        }
    }
}

// ==================== launch ====================
extern "C" void kernel_launch(void* const* d_in, const int* in_sizes, int n_in,
                              void* d_out, int out_size)
{
    const float* q     = (const float*)d_in[0];
    const float* k     = (const float*)d_in[1];
    const float* v     = (const float*)d_in[2];
    const int*   vmask = (const int*)d_in[3];
    const int*   qmask = (const int*)d_in[4];
    const float* Wq = (const float*)d_in[6];
    const float* bq = (const float*)d_in[7];
    const float* Wk = (const float*)d_in[8];
    const float* bk = (const float*)d_in[9];
    const float* Wv = (const float*)d_in[10];
    const float* bv = (const float*)d_in[11];
    const float* Wo = (const float*)d_in[12];
    const float* bo = (const float*)d_in[13];
    float* out = (float*)d_out;

    const int N8 = 4194304 / 8;   // 8 floats per thread
    conv_split3<<<dim3(N8 / 256, 1, 3), 256>>>(q, k, v, N8);
    convT_split4<<<dim3(32, 32, 4), dim3(32, 8)>>>(Wq, Wk, Wv, Wo);

    const int GEMM_SMEM = 2 * STAGE_B;   // 81,920 B
    cudaFuncSetAttribute(tc_gemm_qkv,
                         cudaFuncAttributeMaxDynamicSharedMemorySize, GEMM_SMEM);
    cudaFuncSetAttribute(tc_gemm_final,
                         cudaFuncAttributeMaxDynamicSharedMemorySize, GEMM_SMEM);
    tc_gemm_qkv<<<dim3(8, 32, 3), 256, GEMM_SMEM>>>(bq, bk, bv);

    const int ATTN_SMEM = 8 * STB + 2 * 128 * (int)sizeof(float);  // 148,480 B
    cudaFuncSetAttribute(attn_tc,
                         cudaFuncAttributeMaxDynamicSharedMemorySize, ATTN_SMEM);
    attn_tc<<<512, 256, ATTN_SMEM>>>(vmask);
    attn_fixup<<<dim3(4, 16), 256>>>(vmask);

    tc_gemm_final<<<dim3(8, 32), 256, GEMM_SMEM>>>(bo, qmask, out);
}